// round 1
// baseline (speedup 1.0000x reference)
#include <cuda_runtime.h>
#include <cstdint>

#define VOCAB   32000
#define EMB_DIM 2048
#define N_COMP  64
#define SEQ_L   128
#define BATCH   4096

// ---------------------------------------------------------------------------
// Scratch for pooled embeddings: [N_COMP, EMB_DIM] fp32 (512 KB, static — no alloc)
// ---------------------------------------------------------------------------
__device__ float g_pooled[N_COMP * EMB_DIM];

// ---------------------------------------------------------------------------
// Kernel 1: per-component embedding gather + mean pool.
// grid = (N_COMP, 4), block = 128 threads. Each thread owns one float4 column.
// ---------------------------------------------------------------------------
__global__ void pool_kernel(const int* __restrict__ ids,
                            const float* __restrict__ emb) {
    __shared__ int s_ids[SEQ_L];
    const int comp = blockIdx.x;
    const int t = threadIdx.x;
    if (t < SEQ_L) s_ids[t] = ids[comp * SEQ_L + t];
    __syncthreads();

    const int col4 = blockIdx.y * 128 + t;        // float4 column index (0..511)
    const float4* __restrict__ emb4 = (const float4*)emb;

    float4 acc = make_float4(0.f, 0.f, 0.f, 0.f);
#pragma unroll 8
    for (int l = 0; l < SEQ_L; l++) {
        const int row = s_ids[l];
        float4 v = __ldg(&emb4[(size_t)row * (EMB_DIM / 4) + col4]);
        acc.x += v.x; acc.y += v.y; acc.z += v.z; acc.w += v.w;
    }
    const float inv = 1.0f / (float)SEQ_L;
    acc.x *= inv; acc.y *= inv; acc.z *= inv; acc.w *= inv;
    ((float4*)g_pooled)[comp * (EMB_DIM / 4) + col4] = acc;
}

// ---------------------------------------------------------------------------
// Packed f32x2 helpers (FFMA2 — only reachable via PTX fma.rn.f32x2)
// ---------------------------------------------------------------------------
__device__ __forceinline__ unsigned long long pack2(float lo, float hi) {
    unsigned long long r;
    asm("mov.b64 %0, {%1, %2};" : "=l"(r) : "f"(lo), "f"(hi));
    return r;
}
__device__ __forceinline__ void fma2(unsigned long long& d,
                                     unsigned long long a,
                                     unsigned long long b) {
    asm("fma.rn.f32x2 %0, %1, %2, %0;" : "+l"(d) : "l"(a), "l"(b));
}
__device__ __forceinline__ void unpack2(unsigned long long v, float& lo, float& hi) {
    asm("mov.b64 {%0, %1}, %2;" : "=f"(lo), "=f"(hi) : "l"(v));
}

// ---------------------------------------------------------------------------
// Kernel 2: out[B, D] = ratio[B, 64] @ g_pooled[64, D]
// Block tile: 128 B-rows x 128 D-cols. 256 threads, each 8b x 8d register tile.
// Dynamic smem: pooled tile [64][128] (32 KB) + transposed ratio [64][132] (33 KB).
// ---------------------------------------------------------------------------
#define DT 128
#define BT 128
#define TD 8
#define TB 8
#define RT_STRIDE 132   // 132 % 4 == 0 -> rows stay 16B-aligned for float4 reads

__global__ void __launch_bounds__(256, 2)
mix_kernel(const float* __restrict__ ratio, float* __restrict__ out) {
    extern __shared__ float sm[];
    float* s_pool = sm;                       // [N_COMP][DT]
    float* s_rt   = sm + N_COMP * DT;         // [N_COMP][RT_STRIDE]

    const int dBase = blockIdx.x * DT;
    const int bBase = blockIdx.y * BT;
    const int tid = threadIdx.x;              // 0..255

    // --- load pooled tile: 64 x 128 floats = 2048 float4, coalesced ---
    {
        const float4* __restrict__ pg = (const float4*)g_pooled;
        float4* sp4 = (float4*)s_pool;
#pragma unroll
        for (int i = 0; i < 8; i++) {
            const int idx = i * 256 + tid;        // 0..2047
            const int k = idx >> 5;               // row (DT/4 = 32 float4/row)
            const int c = idx & 31;
            sp4[idx] = pg[k * (EMB_DIM / 4) + (dBase >> 2) + c];
        }
    }
    // --- load ratio tile transposed: s_rt[k][b] = ratio[bBase+b][k] ---
    // Mapping: consecutive lanes -> consecutive b (STS conflict-free; LDG hits L2).
    {
        const float4* __restrict__ rg = (const float4*)ratio;
#pragma unroll
        for (int i = 0; i < 8; i++) {
            const int idx = i * 256 + tid;        // 0..2047
            const int b  = idx & 127;
            const int kk = idx >> 7;              // 0..15 (float4 along K)
            float4 v = __ldg(&rg[(size_t)(bBase + b) * (N_COMP / 4) + kk]);
            s_rt[(4 * kk + 0) * RT_STRIDE + b] = v.x;
            s_rt[(4 * kk + 1) * RT_STRIDE + b] = v.y;
            s_rt[(4 * kk + 2) * RT_STRIDE + b] = v.z;
            s_rt[(4 * kk + 3) * RT_STRIDE + b] = v.w;
        }
    }
    __syncthreads();

    const int dx = (tid & 15) * TD;   // 0..120
    const int by = (tid >> 4) * TB;   // 0..120

    unsigned long long acc[TB][TD / 2];
#pragma unroll
    for (int b = 0; b < TB; b++)
#pragma unroll
        for (int d = 0; d < TD / 2; d++) acc[b][d] = 0ULL;

#pragma unroll 8
    for (int k = 0; k < N_COMP; k++) {
        const float4 p0 = *(const float4*)&s_pool[k * DT + dx];
        const float4 p1 = *(const float4*)&s_pool[k * DT + dx + 4];
        unsigned long long pp[4];
        pp[0] = pack2(p0.x, p0.y); pp[1] = pack2(p0.z, p0.w);
        pp[2] = pack2(p1.x, p1.y); pp[3] = pack2(p1.z, p1.w);

        const float4 r0 = *(const float4*)&s_rt[k * RT_STRIDE + by];
        const float4 r1 = *(const float4*)&s_rt[k * RT_STRIDE + by + 4];
        const float rr[TB] = {r0.x, r0.y, r0.z, r0.w, r1.x, r1.y, r1.z, r1.w};

#pragma unroll
        for (int b = 0; b < TB; b++) {
            const unsigned long long rb = pack2(rr[b], rr[b]);
#pragma unroll
            for (int d = 0; d < TD / 2; d++) fma2(acc[b][d], rb, pp[d]);
        }
    }

    // --- epilogue: each thread writes a contiguous 32B span per b-row ---
#pragma unroll
    for (int b = 0; b < TB; b++) {
        float o[TD];
#pragma unroll
        for (int d = 0; d < TD / 2; d++) unpack2(acc[b][d], o[2 * d], o[2 * d + 1]);
        float4* dst = (float4*)&out[(size_t)(bBase + by + b) * EMB_DIM + dBase + dx];
        dst[0] = make_float4(o[0], o[1], o[2], o[3]);
        dst[1] = make_float4(o[4], o[5], o[6], o[7]);
    }
}

// ---------------------------------------------------------------------------
// Launch
// ---------------------------------------------------------------------------
extern "C" void kernel_launch(void* const* d_in, const int* in_sizes, int n_in,
                              void* d_out, int out_size) {
    const int* ids = nullptr;
    const float* ratio = nullptr;
    const float* emb = nullptr;
    for (int i = 0; i < n_in; i++) {
        if (in_sizes[i] == N_COMP * SEQ_L)      ids   = (const int*)d_in[i];
        else if (in_sizes[i] == BATCH * N_COMP) ratio = (const float*)d_in[i];
        else                                     emb   = (const float*)d_in[i];
    }
    float* out = (float*)d_out;

    // Kernel 1: pool
    {
        dim3 grid(N_COMP, 4);
        pool_kernel<<<grid, 128>>>(ids, emb);
    }

    // Kernel 2: mix (dynamic smem > 48 KB -> opt-in)
    {
        const int smem_bytes = (N_COMP * DT + N_COMP * RT_STRIDE) * (int)sizeof(float);
        static bool attr_set = false;
        if (!attr_set) {
            cudaFuncSetAttribute(mix_kernel,
                                 cudaFuncAttributeMaxDynamicSharedMemorySize,
                                 smem_bytes);
            attr_set = true;
        }
        dim3 grid(EMB_DIM / DT, BATCH / BT);   // (16, 32)
        mix_kernel<<<grid, 256, smem_bytes>>>(ratio, out);
    }
}

// round 4
// speedup vs baseline: 1.1941x; 1.1941x over previous
#include <cuda_runtime.h>
#include <cuda_bf16.h>
#include <cstdint>

#define VOCAB   32000
#define EMB_DIM 2048
#define N_COMP  64
#define SEQ_L   128
#define BATCH   4096
#define SPLIT   4

// ---------------------------------------------------------------------------
// Static scratch (no allocation)
// ---------------------------------------------------------------------------
__device__ float         g_part[SPLIT][N_COMP * EMB_DIM];   // pool partials (2 MB)
__device__ __nv_bfloat16 g_BT_hi[EMB_DIM * N_COMP];         // pooled^T hi [n][k]
__device__ __nv_bfloat16 g_BT_lo[EMB_DIM * N_COMP];         // pooled^T lo [n][k]
__device__ __nv_bfloat16 g_A_hi[BATCH * N_COMP];            // ratio hi [b][k]
__device__ __nv_bfloat16 g_A_lo[BATCH * N_COMP];            // ratio lo [b][k]

// ---------------------------------------------------------------------------
// Kernel 1: pooled partial sums. grid=(N_COMP, 4, SPLIT), block=128.
// ---------------------------------------------------------------------------
__global__ void pool_kernel(const int* __restrict__ ids,
                            const float* __restrict__ emb) {
    __shared__ int s_ids[SEQ_L / SPLIT];
    const int comp = blockIdx.x;
    const int z = blockIdx.z;
    const int t = threadIdx.x;
    const int TOK = SEQ_L / SPLIT;              // 32
    if (t < TOK) s_ids[t] = ids[comp * SEQ_L + z * TOK + t];
    __syncthreads();

    const int col4 = blockIdx.y * 128 + t;      // 0..511
    const float4* __restrict__ emb4 = (const float4*)emb;

    float4 acc = make_float4(0.f, 0.f, 0.f, 0.f);
#pragma unroll 8
    for (int l = 0; l < TOK; l++) {
        const int row = s_ids[l];
        float4 v = __ldg(&emb4[(size_t)row * (EMB_DIM / 4) + col4]);
        acc.x += v.x; acc.y += v.y; acc.z += v.z; acc.w += v.w;
    }
    ((float4*)g_part[z])[comp * (EMB_DIM / 4) + col4] = acc;
}

// ---------------------------------------------------------------------------
// bf16 split helpers
// ---------------------------------------------------------------------------
__device__ __forceinline__ void split_bf16(float v, __nv_bfloat16& hi, __nv_bfloat16& lo) {
    hi = __float2bfloat16_rn(v);
    lo = __float2bfloat16_rn(v - __bfloat162float(hi));
}
__device__ __forceinline__ uint32_t pack_bf2(__nv_bfloat16 a, __nv_bfloat16 b) {
    __nv_bfloat162 h = __halves2bfloat162(a, b);
    return *reinterpret_cast<uint32_t*>(&h);
}

// ---------------------------------------------------------------------------
// Kernel 2: fused converts. blocks 0..7: pooled reduce+scale+split+transpose.
//           blocks 8..263: ratio fp32 -> bf16 hi/lo.
// ---------------------------------------------------------------------------
__global__ void cvt_kernel(const float* __restrict__ ratio) {
    const int bx = blockIdx.x;
    if (bx < 8) {
        // thread owns one n column (2048 total), loops k = 0..63
        const int n = bx * 256 + threadIdx.x;
        uint32_t h2[N_COMP / 2], l2[N_COMP / 2];
#pragma unroll
        for (int kp = 0; kp < N_COMP / 2; kp++) {
            __nv_bfloat16 ha, la, hb, lb;
            {
                const int k = 2 * kp;
                float s = g_part[0][k * EMB_DIM + n] + g_part[1][k * EMB_DIM + n]
                        + g_part[2][k * EMB_DIM + n] + g_part[3][k * EMB_DIM + n];
                split_bf16(s * (1.0f / SEQ_L), ha, la);
            }
            {
                const int k = 2 * kp + 1;
                float s = g_part[0][k * EMB_DIM + n] + g_part[1][k * EMB_DIM + n]
                        + g_part[2][k * EMB_DIM + n] + g_part[3][k * EMB_DIM + n];
                split_bf16(s * (1.0f / SEQ_L), hb, lb);
            }
            h2[kp] = pack_bf2(ha, hb);
            l2[kp] = pack_bf2(la, lb);
        }
        uint4* dh = (uint4*)g_BT_hi;   // row n = 8 uint4 (64 bf16)
        uint4* dl = (uint4*)g_BT_lo;
#pragma unroll
        for (int c = 0; c < 8; c++) {
            dh[n * 8 + c] = make_uint4(h2[4*c], h2[4*c+1], h2[4*c+2], h2[4*c+3]);
            dl[n * 8 + c] = make_uint4(l2[4*c], l2[4*c+1], l2[4*c+2], l2[4*c+3]);
        }
    } else {
        const int gid = (bx - 8) * 256 + threadIdx.x;      // 0..65535 float4s
        float4 v = __ldg(&((const float4*)ratio)[gid]);
        __nv_bfloat16 h0, l0, h1, l1, h2, l2, h3, l3;
        split_bf16(v.x, h0, l0); split_bf16(v.y, h1, l1);
        split_bf16(v.z, h2, l2); split_bf16(v.w, h3, l3);
        ((uint2*)g_A_hi)[gid] = make_uint2(pack_bf2(h0, h1), pack_bf2(h2, h3));
        ((uint2*)g_A_lo)[gid] = make_uint2(pack_bf2(l0, l1), pack_bf2(l2, l3));
    }
}

// ---------------------------------------------------------------------------
// Kernel 3: HMMA mix. out[B,D] = ratio @ pooled via bf16-split (hh + hl + lh).
// CTA: 128 b-rows x 128 d-cols, 256 threads (8 warps, 4 along m x 2 along n).
// Warp: 32m x 64n = 2 m-tiles x 8 n-tiles of m16n8k16.
// A frags from global (L2/L1-hot), B frags from 144B-padded smem.
// ---------------------------------------------------------------------------
#define MMA16816(c, a, b0, b1) \
    asm volatile("mma.sync.aligned.m16n8k16.row.col.f32.bf16.bf16.f32 " \
        "{%0,%1,%2,%3}, {%4,%5,%6,%7}, {%8,%9}, {%0,%1,%2,%3};" \
        : "+f"((c)[0]), "+f"((c)[1]), "+f"((c)[2]), "+f"((c)[3]) \
        : "r"((a)[0]), "r"((a)[1]), "r"((a)[2]), "r"((a)[3]), "r"(b0), "r"(b1))

#define BSTRIDE 72   // bf16 elems per smem row (144 B) -> conflict-free LDS.32

__global__ void __launch_bounds__(256, 2)
mix_kernel(float* __restrict__ out) {
    __shared__ __nv_bfloat16 sBh[128 * BSTRIDE];
    __shared__ __nv_bfloat16 sBl[128 * BSTRIDE];

    const int tid = threadIdx.x;
    const int wid = tid >> 5;
    const int lane = tid & 31;
    const int g = lane >> 2;          // 0..7
    const int t = lane & 3;           // 0..3
    const int dBase = blockIdx.x * 128;
    const int bBase = blockIdx.y * 128;

    // --- fill B smem: 128 rows x 8 int4 (64 bf16 = 128 B) per row ---
    {
        const int4* __restrict__ bh = (const int4*)g_BT_hi;
        const int4* __restrict__ bl = (const int4*)g_BT_lo;
#pragma unroll
        for (int i = 0; i < 4; i++) {
            const int idx = i * 256 + tid;          // 0..1023
            const int r = idx >> 3, c = idx & 7;    // row 0..127, chunk 0..7
            *(int4*)((char*)sBh + r * 144 + c * 16) = __ldg(&bh[(size_t)(dBase + r) * 8 + c]);
            *(int4*)((char*)sBl + r * 144 + c * 16) = __ldg(&bl[(size_t)(dBase + r) * 8 + c]);
        }
    }
    __syncthreads();

    const int wm = wid & 3;           // 0..3 (m)
    const int wn = wid >> 2;          // 0..1 (n)
    const int mrow0 = bBase + wm * 32;

    float acc[2][8][4];
#pragma unroll
    for (int mt = 0; mt < 2; mt++)
#pragma unroll
        for (int nt = 0; nt < 8; nt++)
#pragma unroll
            for (int q = 0; q < 4; q++) acc[mt][nt][q] = 0.f;

    const uint32_t* __restrict__ Ah = (const uint32_t*)g_A_hi;  // [b][32] bf16-pairs
    const uint32_t* __restrict__ Al = (const uint32_t*)g_A_lo;

#pragma unroll
    for (int ks = 0; ks < 4; ks++) {
        const int k0 = ks * 16;
        const int kp = k0 / 2;        // uint32 pair index

        uint32_t ah[2][4], al[2][4];
#pragma unroll
        for (int mt = 0; mt < 2; mt++) {
            const int r0 = mrow0 + mt * 16 + g;
            ah[mt][0] = __ldg(&Ah[(size_t)r0 * 32 + kp + t]);
            ah[mt][1] = __ldg(&Ah[(size_t)(r0 + 8) * 32 + kp + t]);
            ah[mt][2] = __ldg(&Ah[(size_t)r0 * 32 + kp + 4 + t]);
            ah[mt][3] = __ldg(&Ah[(size_t)(r0 + 8) * 32 + kp + 4 + t]);
            al[mt][0] = __ldg(&Al[(size_t)r0 * 32 + kp + t]);
            al[mt][1] = __ldg(&Al[(size_t)(r0 + 8) * 32 + kp + t]);
            al[mt][2] = __ldg(&Al[(size_t)r0 * 32 + kp + 4 + t]);
            al[mt][3] = __ldg(&Al[(size_t)(r0 + 8) * 32 + kp + 4 + t]);
        }

#pragma unroll
        for (int nt = 0; nt < 8; nt++) {
            const int nrow = wn * 64 + nt * 8 + g;
            const char* ph = (const char*)sBh + nrow * 144;
            const char* pl = (const char*)sBl + nrow * 144;
            const uint32_t bh0 = *(const uint32_t*)(ph + (k0 + t * 2) * 2);
            const uint32_t bh1 = *(const uint32_t*)(ph + (k0 + 8 + t * 2) * 2);
            const uint32_t bl0 = *(const uint32_t*)(pl + (k0 + t * 2) * 2);
            const uint32_t bl1 = *(const uint32_t*)(pl + (k0 + 8 + t * 2) * 2);
#pragma unroll
            for (int mt = 0; mt < 2; mt++) {
                MMA16816(acc[mt][nt], ah[mt], bh0, bh1);   // hi*hi
                MMA16816(acc[mt][nt], ah[mt], bl0, bl1);   // hi*lo
                MMA16816(acc[mt][nt], al[mt], bh0, bh1);   // lo*hi
            }
        }
    }

    // --- epilogue: direct float2 stores ---
#pragma unroll
    for (int mt = 0; mt < 2; mt++) {
        const int m = mrow0 + mt * 16 + g;
#pragma unroll
        for (int nt = 0; nt < 8; nt++) {
            const int col = dBase + wn * 64 + nt * 8 + t * 2;
            *(float2*)&out[(size_t)m * EMB_DIM + col] =
                make_float2(acc[mt][nt][0], acc[mt][nt][1]);
            *(float2*)&out[(size_t)(m + 8) * EMB_DIM + col] =
                make_float2(acc[mt][nt][2], acc[mt][nt][3]);
        }
    }
}

// ---------------------------------------------------------------------------
// Launch
// ---------------------------------------------------------------------------
extern "C" void kernel_launch(void* const* d_in, const int* in_sizes, int n_in,
                              void* d_out, int out_size) {
    const int* ids = nullptr;
    const float* ratio = nullptr;
    const float* emb = nullptr;
    for (int i = 0; i < n_in; i++) {
        if (in_sizes[i] == N_COMP * SEQ_L)      ids   = (const int*)d_in[i];
        else if (in_sizes[i] == BATCH * N_COMP) ratio = (const float*)d_in[i];
        else                                     emb   = (const float*)d_in[i];
    }
    float* out = (float*)d_out;

    {   // pool partials
        dim3 grid(N_COMP, 4, SPLIT);
        pool_kernel<<<grid, 128>>>(ids, emb);
    }
    {   // reduce/split/transpose pooled + convert ratio
        cvt_kernel<<<8 + (BATCH * N_COMP / 4) / 256, 256>>>(ratio);
    }
    {   // HMMA mix
        dim3 grid(EMB_DIM / 128, BATCH / 128);   // (16, 32)
        mix_kernel<<<grid, 256>>>(out);
    }
}

// round 5
// speedup vs baseline: 1.5278x; 1.2794x over previous
#include <cuda_runtime.h>
#include <cuda_bf16.h>
#include <cstdint>

#define VOCAB   32000
#define EMB_DIM 2048
#define N_COMP  64
#define SEQ_L   128
#define BATCH   4096
#define SPLIT   8

// ---------------------------------------------------------------------------
// Static scratch (no allocation)
// ---------------------------------------------------------------------------
__device__ float         g_part[SPLIT][N_COMP * EMB_DIM];   // pool partials (4 MB)
__device__ __nv_bfloat16 g_BT_hi[EMB_DIM * N_COMP];         // pooled^T hi [n][k]
__device__ __nv_bfloat16 g_BT_lo[EMB_DIM * N_COMP];         // pooled^T lo [n][k]

// ---------------------------------------------------------------------------
// Kernel 1: pooled partial sums. grid=(N_COMP, 4, SPLIT), block=128.
// ---------------------------------------------------------------------------
__global__ void pool_kernel(const int* __restrict__ ids,
                            const float* __restrict__ emb) {
    __shared__ int s_ids[SEQ_L / SPLIT];
    const int comp = blockIdx.x;
    const int z = blockIdx.z;
    const int t = threadIdx.x;
    const int TOK = SEQ_L / SPLIT;              // 16
    if (t < TOK) s_ids[t] = ids[comp * SEQ_L + z * TOK + t];
    __syncthreads();

    const int col4 = blockIdx.y * 128 + t;      // 0..511
    const float4* __restrict__ emb4 = (const float4*)emb;

    float4 acc = make_float4(0.f, 0.f, 0.f, 0.f);
#pragma unroll
    for (int l = 0; l < TOK; l++) {
        const int row = s_ids[l];
        float4 v = __ldg(&emb4[(size_t)row * (EMB_DIM / 4) + col4]);
        acc.x += v.x; acc.y += v.y; acc.z += v.z; acc.w += v.w;
    }
    ((float4*)g_part[z])[comp * (EMB_DIM / 4) + col4] = acc;
}

// ---------------------------------------------------------------------------
// bf16 split helpers
// ---------------------------------------------------------------------------
__device__ __forceinline__ void split_bf16(float v, __nv_bfloat16& hi, __nv_bfloat16& lo) {
    hi = __float2bfloat16_rn(v);
    lo = __float2bfloat16_rn(v - __bfloat162float(hi));
}
__device__ __forceinline__ uint32_t pack_bf2(__nv_bfloat16 a, __nv_bfloat16 b) {
    __nv_bfloat162 h = __halves2bfloat162(a, b);
    return *reinterpret_cast<uint32_t*>(&h);
}

// ---------------------------------------------------------------------------
// Kernel 2: pooled reduce + scale + bf16 split + transpose.
// grid=64, block=128. Warp lane = n column (coalesced partial reads);
// threadIdx.y quarter = 16-k slice.
// ---------------------------------------------------------------------------
__global__ void cvt_kernel() {
    const int lane = threadIdx.x & 31;
    const int ty = threadIdx.x >> 5;            // 0..3
    const int n = blockIdx.x * 32 + lane;       // 0..2047
    const int k0 = ty * 16;

    uint32_t h2[8], l2[8];
#pragma unroll
    for (int kp = 0; kp < 8; kp++) {
        __nv_bfloat16 ha, la, hb, lb;
        {
            const int k = k0 + 2 * kp;
            float s = 0.f;
#pragma unroll
            for (int z = 0; z < SPLIT; z++) s += g_part[z][k * EMB_DIM + n];
            split_bf16(s * (1.0f / SEQ_L), ha, la);
        }
        {
            const int k = k0 + 2 * kp + 1;
            float s = 0.f;
#pragma unroll
            for (int z = 0; z < SPLIT; z++) s += g_part[z][k * EMB_DIM + n];
            split_bf16(s * (1.0f / SEQ_L), hb, lb);
        }
        h2[kp] = pack_bf2(ha, hb);
        l2[kp] = pack_bf2(la, lb);
    }
    uint4* dh = (uint4*)g_BT_hi;   // row n = 8 uint4 (64 bf16)
    uint4* dl = (uint4*)g_BT_lo;
#pragma unroll
    for (int c = 0; c < 2; c++) {
        dh[n * 8 + ty * 2 + c] = make_uint4(h2[4*c], h2[4*c+1], h2[4*c+2], h2[4*c+3]);
        dl[n * 8 + ty * 2 + c] = make_uint4(l2[4*c], l2[4*c+1], l2[4*c+2], l2[4*c+3]);
    }
}

// ---------------------------------------------------------------------------
// Kernel 3: HMMA mix with ldmatrix fragment loads.
// out[B,D] = ratio @ pooled via bf16-split (hh + hl + lh).
// CTA: 128 b-rows x 128 d-cols, 256 threads (4 warps m x 2 warps n).
// smem: A hi/lo + B hi/lo, 144B-padded rows (conflict-free LDSM).
// A tile staged from fp32 ratio with the hi/lo split fused in.
// ---------------------------------------------------------------------------
#define MMA16816(c, a, b0, b1) \
    asm volatile("mma.sync.aligned.m16n8k16.row.col.f32.bf16.bf16.f32 " \
        "{%0,%1,%2,%3}, {%4,%5,%6,%7}, {%8,%9}, {%0,%1,%2,%3};" \
        : "+f"((c)[0]), "+f"((c)[1]), "+f"((c)[2]), "+f"((c)[3]) \
        : "r"((a)[0]), "r"((a)[1]), "r"((a)[2]), "r"((a)[3]), "r"(b0), "r"(b1))

#define LDSM_X4(r0, r1, r2, r3, addr) \
    asm volatile("ldmatrix.sync.aligned.m8n8.x4.shared.b16 {%0,%1,%2,%3}, [%4];" \
        : "=r"(r0), "=r"(r1), "=r"(r2), "=r"(r3) : "r"(addr))

#define ROWB 144            // padded row pitch in bytes (72 bf16)
#define OFF_AH 0
#define OFF_AL (128 * ROWB)
#define OFF_BH (2 * 128 * ROWB)
#define OFF_BL (3 * 128 * ROWB)
#define MIX_SMEM (4 * 128 * ROWB)   // 73728 B

__device__ __forceinline__ uint32_t smem_u32(const void* p) {
    uint32_t a;
    asm("{ .reg .u64 t; cvta.to.shared.u64 t, %1; cvt.u32.u64 %0, t; }" : "=r"(a) : "l"(p));
    return a;
}

__global__ void __launch_bounds__(256)
mix_kernel(const float* __restrict__ ratio, float* __restrict__ out) {
    extern __shared__ char smem[];
    const uint32_t sb = smem_u32(smem);

    const int tid = threadIdx.x;
    const int wid = tid >> 5;
    const int lane = tid & 31;
    const int g = lane >> 2;          // 0..7
    const int t = lane & 3;           // 0..3
    const int dBase = blockIdx.x * 128;
    const int bBase = blockIdx.y * 128;

    // --- stage A: ratio[bBase..+128][0..64] fp32 -> bf16 hi/lo in smem ---
    {
        const float4* __restrict__ rg = (const float4*)ratio;
#pragma unroll
        for (int i = 0; i < 8; i++) {
            const int idx = i * 256 + tid;          // 0..2047
            const int b = idx >> 4;                 // row 0..127
            const int c = idx & 15;                 // float4 (4 cols)
            float4 v = __ldg(&rg[(size_t)(bBase + b) * 16 + c]);
            __nv_bfloat16 h0, l0, h1, l1, h2, l2, h3, l3;
            split_bf16(v.x, h0, l0); split_bf16(v.y, h1, l1);
            split_bf16(v.z, h2, l2); split_bf16(v.w, h3, l3);
            const int off = b * ROWB + c * 8;
            *(uint2*)(smem + OFF_AH + off) = make_uint2(pack_bf2(h0, h1), pack_bf2(h2, h3));
            *(uint2*)(smem + OFF_AL + off) = make_uint2(pack_bf2(l0, l1), pack_bf2(l2, l3));
        }
    }
    // --- stage B: g_BT rows dBase..+128, 8 int4 per row ---
    {
        const int4* __restrict__ bh = (const int4*)g_BT_hi;
        const int4* __restrict__ bl = (const int4*)g_BT_lo;
#pragma unroll
        for (int i = 0; i < 4; i++) {
            const int idx = i * 256 + tid;          // 0..1023
            const int r = idx >> 3, c = idx & 7;
            const int off = r * ROWB + c * 16;
            *(int4*)(smem + OFF_BH + off) = __ldg(&bh[(size_t)(dBase + r) * 8 + c]);
            *(int4*)(smem + OFF_BL + off) = __ldg(&bl[(size_t)(dBase + r) * 8 + c]);
        }
    }
    __syncthreads();

    const int wm = wid & 3;           // m warp (0..3)
    const int wn = wid >> 2;          // n warp (0..1)

    // ldmatrix lane address components
    const int lr = lane & 7;
    const int seg = lane >> 3;        // 0..3
    const int row_off = (seg & 1) * 8 + lr;     // +8 rows for segs 1,3
    const int k_off = (seg >> 1) * 8;           // +8 k for segs 2,3

    float acc[2][8][4];
#pragma unroll
    for (int mt = 0; mt < 2; mt++)
#pragma unroll
        for (int nt = 0; nt < 8; nt++)
#pragma unroll
            for (int q = 0; q < 4; q++) acc[mt][nt][q] = 0.f;

#pragma unroll
    for (int ks = 0; ks < 4; ks++) {
        const int k0 = ks * 16;
        const int kb = (k0 + k_off) * 2;        // byte offset along k

        uint32_t ah[2][4], al[2][4];
#pragma unroll
        for (int mt = 0; mt < 2; mt++) {
            const int m = wm * 32 + mt * 16 + row_off;
            LDSM_X4(ah[mt][0], ah[mt][1], ah[mt][2], ah[mt][3], sb + OFF_AH + m * ROWB + kb);
            LDSM_X4(al[mt][0], al[mt][1], al[mt][2], al[mt][3], sb + OFF_AL + m * ROWB + kb);
        }

#pragma unroll
        for (int p = 0; p < 4; p++) {           // each p covers nt = 2p, 2p+1
            const int n = wn * 64 + p * 16 + row_off;
            uint32_t bh0, bh1, bh2, bh3, bl0, bl1, bl2, bl3;
            LDSM_X4(bh0, bh1, bh2, bh3, sb + OFF_BH + n * ROWB + kb);
            LDSM_X4(bl0, bl1, bl2, bl3, sb + OFF_BL + n * ROWB + kb);
            // r0 = b0(nt=2p), r1 = b0(nt=2p+1), r2 = b1(2p), r3 = b1(2p+1)
#pragma unroll
            for (int mt = 0; mt < 2; mt++) {
                MMA16816(acc[mt][2*p],   ah[mt], bh0, bh2);   // hi*hi
                MMA16816(acc[mt][2*p],   ah[mt], bl0, bl2);   // hi*lo
                MMA16816(acc[mt][2*p],   al[mt], bh0, bh2);   // lo*hi
                MMA16816(acc[mt][2*p+1], ah[mt], bh1, bh3);
                MMA16816(acc[mt][2*p+1], ah[mt], bl1, bl3);
                MMA16816(acc[mt][2*p+1], al[mt], bh1, bh3);
            }
        }
    }

    // --- epilogue: direct float2 stores ---
#pragma unroll
    for (int mt = 0; mt < 2; mt++) {
        const int m = bBase + wm * 32 + mt * 16 + g;
#pragma unroll
        for (int nt = 0; nt < 8; nt++) {
            const int col = dBase + wn * 64 + nt * 8 + t * 2;
            *(float2*)&out[(size_t)m * EMB_DIM + col] =
                make_float2(acc[mt][nt][0], acc[mt][nt][1]);
            *(float2*)&out[(size_t)(m + 8) * EMB_DIM + col] =
                make_float2(acc[mt][nt][2], acc[mt][nt][3]);
        }
    }
}

// ---------------------------------------------------------------------------
// Launch
// ---------------------------------------------------------------------------
extern "C" void kernel_launch(void* const* d_in, const int* in_sizes, int n_in,
                              void* d_out, int out_size) {
    const int* ids = nullptr;
    const float* ratio = nullptr;
    const float* emb = nullptr;
    for (int i = 0; i < n_in; i++) {
        if (in_sizes[i] == N_COMP * SEQ_L)      ids   = (const int*)d_in[i];
        else if (in_sizes[i] == BATCH * N_COMP) ratio = (const float*)d_in[i];
        else                                     emb   = (const float*)d_in[i];
    }
    float* out = (float*)d_out;

    {   // pool partials
        dim3 grid(N_COMP, 4, SPLIT);            // 2048 blocks
        pool_kernel<<<grid, 128>>>(ids, emb);
    }
    {   // pooled reduce/split/transpose
        cvt_kernel<<<64, 128>>>();
    }
    {   // HMMA mix
        static bool attr_set = false;
        if (!attr_set) {
            cudaFuncSetAttribute(mix_kernel,
                                 cudaFuncAttributeMaxDynamicSharedMemorySize,
                                 MIX_SMEM);
            attr_set = true;
        }
        dim3 grid(EMB_DIM / 128, BATCH / 128);  // (16, 32)
        mix_kernel<<<grid, 256, MIX_SMEM>>>(ratio, out);
    }
}